// round 4
// baseline (speedup 1.0000x reference)
#include <cuda_runtime.h>

// ProportionalNeuron: leaky-integrate-and-fire scan.
//   ff  = x[t,b,f] * W[f,f]   (W == 0.4*I exactly -> matmul is bit-exact elementwise)
//   i   = leak_i * i + ff
//   v   = leak_v * v * (1-z) + i     ((1-z) in {0,1} exactly)
//   z   = (v - thresh > 0) ? 1 : 0
//
// R3 -> R4: float4 vectorization. One thread owns 4 consecutive neurons:
// LDG.128/STG.128 move 4x bytes per issued memory op, recurrence becomes 4
// independent chains (ILP 4x inside the ~16cyc serial dependency window),
// LDG count /4 keeps outstanding loads under the ~55/warp cap at PF=32.
// Per-neuron arithmetic unchanged -> rel_err identical.

#define T_STEPS 2048
#define B_DIM   64
#define F_DIM   512
#define N_NEUR  (B_DIM * F_DIM)       // 32768
#define N_VEC   (N_NEUR / 4)          // 8192 float4 lanes
#define PF      32                    // prefetch depth (float4 steps)

__global__ __launch_bounds__(32, 1)
void snn_scan_kernel(const float4* __restrict__ x4,
                     const float* __restrict__ W,
                     const float* __restrict__ leak_i,
                     const float* __restrict__ leak_v,
                     const float* __restrict__ thresh,
                     float4* __restrict__ out4)
{
    const int n4 = blockIdx.x * blockDim.x + threadIdx.x;   // 0..8191
    const int f0 = (n4 * 4) & (F_DIM - 1);                  // first of 4 features

    // Per-lane parameters for the 4 neurons
    float wff[4], li[4], lv[4], th[4];
#pragma unroll
    for (int j = 0; j < 4; ++j) {
        const int f = f0 + j;
        wff[j] = W[f * F_DIM + f];   // diagonal; off-diagonal terms are exactly 0
        li[j]  = leak_i[f];
        lv[j]  = leak_v[f];
        th[j]  = thresh[f];
    }

    float i_s[4] = {0.f, 0.f, 0.f, 0.f};
    float v_s[4] = {0.f, 0.f, 0.f, 0.f};
    float z[4]   = {0.f, 0.f, 0.f, 0.f};

    // Prime the prefetch ring
    float4 xb[PF];
#pragma unroll
    for (int k = 0; k < PF; ++k)
        xb[k] = __ldcs(x4 + k * N_VEC + n4);

    // Main loop with unconditional prefetch PF steps ahead
    for (int t = 0; t < T_STEPS - PF; t += PF) {
        const int base = t * N_VEC + n4;
#pragma unroll
        for (int k = 0; k < PF; ++k) {
            const float4 xv = xb[k];
            xb[k] = __ldcs(x4 + base + (k + PF) * N_VEC);

            const float xs[4] = {xv.x, xv.y, xv.z, xv.w};
            float zs[4];
#pragma unroll
            for (int j = 0; j < 4; ++j) {
                const float ff = __fmul_rn(xs[j], wff[j]);
                i_s[j] = __fadd_rn(__fmul_rn(li[j], i_s[j]), ff);
                const float decay = (z[j] > 0.5f) ? 0.0f : __fmul_rn(lv[j], v_s[j]);
                v_s[j] = __fadd_rn(decay, i_s[j]);
                z[j] = (__fadd_rn(v_s[j], -th[j]) > 0.0f) ? 1.0f : 0.0f;
                zs[j] = z[j];
            }
            __stcs(out4 + base + k * N_VEC, make_float4(zs[0], zs[1], zs[2], zs[3]));
        }
    }

    // Epilogue: last PF steps, no prefetch
    {
        const int base = (T_STEPS - PF) * N_VEC + n4;
#pragma unroll
        for (int k = 0; k < PF; ++k) {
            const float4 xv = xb[k];
            const float xs[4] = {xv.x, xv.y, xv.z, xv.w};
            float zs[4];
#pragma unroll
            for (int j = 0; j < 4; ++j) {
                const float ff = __fmul_rn(xs[j], wff[j]);
                i_s[j] = __fadd_rn(__fmul_rn(li[j], i_s[j]), ff);
                const float decay = (z[j] > 0.5f) ? 0.0f : __fmul_rn(lv[j], v_s[j]);
                v_s[j] = __fadd_rn(decay, i_s[j]);
                z[j] = (__fadd_rn(v_s[j], -th[j]) > 0.0f) ? 1.0f : 0.0f;
                zs[j] = z[j];
            }
            __stcs(out4 + base + k * N_VEC, make_float4(zs[0], zs[1], zs[2], zs[3]));
        }
    }
}

extern "C" void kernel_launch(void* const* d_in, const int* in_sizes, int n_in,
                              void* d_out, int out_size)
{
    const float4* x4    = (const float4*)d_in[0];
    const float* W      = (const float*)d_in[1];
    const float* leak_i = (const float*)d_in[2];
    const float* leak_v = (const float*)d_in[3];
    const float* thresh = (const float*)d_in[4];
    float4* out4 = (float4*)d_out;

    const int block = 32;
    const int grid  = N_VEC / block;   // 256 blocks, 256 warps
    snn_scan_kernel<<<grid, block>>>(x4, W, leak_i, leak_v, thresh, out4);
}

// round 5
// speedup vs baseline: 1.4055x; 1.4055x over previous
#include <cuda_runtime.h>

// ProportionalNeuron: leaky-integrate-and-fire scan, one thread per (b,f) neuron.
//   ff  = x[t,b,f] * W[f,f]   (W == 0.4*I exactly -> matmul is bit-exact elementwise)
//   i   = leak_i * i + ff
//   v   = (z ? 0 : leak_v*v) + i       ((1-z) in {0,1} exactly -> select is bit-exact)
//   z   = v > thresh                   (== (v - thresh) > 0 in IEEE fp32)
//
// R4 -> R5: revert float4 regression (scalar = max warp coverage, 1024 warps).
// Cut step body ~13 -> ~10 instr: carry z as predicate (no z>0.5 re-compare),
// compare v>th directly (no FADD), per-outer-iter base pointers keep all 64
// unrolled offsets inside the LDG/STG immediate range. Arithmetic bit-identical.

#define T_STEPS 2048
#define B_DIM   64
#define F_DIM   512
#define N_NEUR  (B_DIM * F_DIM)   // 32768 -> 131072 B per time step
#define PF      64                 // prefetch depth; divides T_STEPS

__global__ __launch_bounds__(32, 8)
void snn_scan_kernel(const float* __restrict__ x,
                     const float* __restrict__ W,
                     const float* __restrict__ leak_i,
                     const float* __restrict__ leak_v,
                     const float* __restrict__ thresh,
                     float* __restrict__ out)
{
    const int n = blockIdx.x * blockDim.x + threadIdx.x;   // 0..32767
    const int f = n & (F_DIM - 1);

    // Diagonal of W (off-diagonal contributions of x@W.T are exactly 0)
    const float wff = W[f * F_DIM + f];
    const float li  = leak_i[f];
    const float lv  = leak_v[f];
    const float th  = thresh[f];

    float i_s = 0.0f;
    float v_s = 0.0f;
    bool  zb  = false;

    // Prime the prefetch ring
    float xb[PF];
    {
        const float* xp = x + n;
#pragma unroll
        for (int k = 0; k < PF; ++k)
            xb[k] = __ldcs(xp + k * N_NEUR);
    }

    // Main loop: unconditional prefetch PF steps ahead.
    for (int t = 0; t < T_STEPS - PF; t += PF) {
        // Base pointers per outer iteration: all unrolled offsets fit the
        // 24-bit LDG/STG immediate (max 63 * 131072 * 4B = 8.26 MB < 8.39 MB).
        const float* xpre = x + (t + PF) * N_NEUR + n;
        float*       op   = out + t * N_NEUR + n;
#pragma unroll
        for (int k = 0; k < PF; ++k) {
            const float xv = xb[k];
            xb[k] = __ldcs(xpre + k * N_NEUR);

            const float ff  = __fmul_rn(xv, wff);
            i_s = __fadd_rn(__fmul_rn(li, i_s), ff);
            const float lvv = __fmul_rn(lv, v_s);
            v_s = __fadd_rn(zb ? 0.0f : lvv, i_s);
            zb  = (v_s > th);

            __stcs(op + k * N_NEUR, zb ? 1.0f : 0.0f);
        }
    }

    // Epilogue: last PF steps, no prefetch
    {
        float* op = out + (T_STEPS - PF) * N_NEUR + n;
#pragma unroll
        for (int k = 0; k < PF; ++k) {
            const float xv = xb[k];

            const float ff  = __fmul_rn(xv, wff);
            i_s = __fadd_rn(__fmul_rn(li, i_s), ff);
            const float lvv = __fmul_rn(lv, v_s);
            v_s = __fadd_rn(zb ? 0.0f : lvv, i_s);
            zb  = (v_s > th);

            __stcs(op + k * N_NEUR, zb ? 1.0f : 0.0f);
        }
    }
}

extern "C" void kernel_launch(void* const* d_in, const int* in_sizes, int n_in,
                              void* d_out, int out_size)
{
    const float* x      = (const float*)d_in[0];
    const float* W      = (const float*)d_in[1];
    const float* leak_i = (const float*)d_in[2];
    const float* leak_v = (const float*)d_in[3];
    const float* thresh = (const float*)d_in[4];
    float* out = (float*)d_out;

    const int block = 32;
    const int grid  = N_NEUR / block;   // 1024 blocks, 1024 warps
    snn_scan_kernel<<<grid, block>>>(x, W, leak_i, leak_v, thresh, out);
}